// round 10
// baseline (speedup 1.0000x reference)
#include <cuda_runtime.h>
#include <cuda_bf16.h>
#include <math.h>
#include <cstdint>

#define BB 8
#define CC 64
#define OO 64
#define HH 96
#define WW 96
#define NN 9
#define HW (HH*WW)            // 9216
#define PIXELS (BB*HH*WW)     // 73728
#define SCR_CH 27

// offset (18) + modulation-raw (9) planes, layout [ch][pixel], bias included
__device__ float g_scr[SCR_CH * PIXELS];
// channel-last copy of x: [b][pix][c], 256B-aligned rows of 64 floats
__device__ __align__(16) float g_xT[PIXELS * CC];
// prepped B for deform: [tap][o(64)][k(192)] bf16, k = [whi | whi | wlo]
__device__ __align__(16) unsigned short g_Bw[NN * 64 * 192];
// prepped B for offconv: [tap][o(32, 27 used)][k(192)] bf16
__device__ __align__(16) unsigned short g_Bw2[NN * 32 * 192];

// bf16 mma: D += A(16x16 row) * B(16x8 col)
__device__ __forceinline__ void mma_bf16(float* d, const uint32_t* a,
                                         uint32_t b0, uint32_t b1) {
    asm volatile(
        "mma.sync.aligned.m16n8k16.row.col.f32.bf16.bf16.f32 "
        "{%0,%1,%2,%3}, {%4,%5,%6,%7}, {%8,%9}, {%0,%1,%2,%3};"
        : "+f"(d[0]), "+f"(d[1]), "+f"(d[2]), "+f"(d[3])
        : "r"(a[0]), "r"(a[1]), "r"(a[2]), "r"(a[3]), "r"(b0), "r"(b1));
}

// split two fp32 into packed bf16 hi + bf16 lo-residual
__device__ __forceinline__ void split2(float v0, float v1,
                                       uint32_t& hp, uint32_t& lp) {
    asm("cvt.rn.satfinite.bf16x2.f32 %0, %1, %2;" : "=r"(hp) : "f"(v1), "f"(v0));
    float h0 = __uint_as_float(hp << 16);
    float h1 = __uint_as_float(hp & 0xffff0000u);
    float l0 = v0 - h0, l1 = v1 - h1;
    asm("cvt.rn.satfinite.bf16x2.f32 %0, %1, %2;" : "=r"(lp) : "f"(l1), "f"(l0));
}

// ---------------------------------------------------------------------------
// Kernel X: transpose x [b][c][pix] -> g_xT [b][pix][c] (channel-last).
// Block: 256 thr handles a 32-pixel x 64-channel tile via smem.
// ---------------------------------------------------------------------------
__global__ void __launch_bounds__(256) k_prepx(const float* __restrict__ x)
{
    __shared__ float t[64][33];
    const int tid = threadIdx.x;
    const int b = blockIdx.y;
    const int pix0 = blockIdx.x * 32;

    int tx = tid & 31, ty = tid >> 5;          // pix lane, ch group
    #pragma unroll
    for (int k = 0; k < 8; k++) {
        int c = ty + 8 * k;
        t[c][tx] = x[((size_t)b * CC + c) * HW + pix0 + tx];
    }
    __syncthreads();

    int c2 = tid & 63, p2 = tid >> 6;          // ch lane, pix group
    #pragma unroll
    for (int k = 0; k < 8; k++) {
        int p = p2 + 4 * k;
        g_xT[((size_t)b * HW + pix0 + p) * CC + c2] = t[c2][p];
    }
}

// ---------------------------------------------------------------------------
// Kernel P: build both B images (hi/lo split, k layout [whi|whi|wlo]).
// ---------------------------------------------------------------------------
__global__ void __launch_bounds__(256) k_prepw(
    const float* __restrict__ cw,
    const float* __restrict__ ow, const float* __restrict__ mw)
{
    int i = blockIdx.x * 256 + threadIdx.x;     // 648*256 = 165888
    float wv;
    unsigned short* dst;
    int k;
    if (i < NN * 64 * 192) {
        int n = i / (64 * 192);
        int rr = i % (64 * 192);
        int o = rr / 192;
        k = rr % 192;
        int c = k & 63;
        wv = cw[(o * CC + c) * NN + n];
        dst = g_Bw + i;
    } else {
        int j = i - NN * 64 * 192;              // 9*32*192 = 55296
        int n = j / (32 * 192);
        int rr = j % (32 * 192);
        int o = rr / 192;
        k = rr % 192;
        int c = k & 63;
        wv = (o < 18) ? ow[(o * CC + c) * 9 + n]
           : (o < 27) ? mw[((o - 18) * CC + c) * 9 + n] : 0.f;
        dst = g_Bw2 + j;
    }
    __nv_bfloat16 hi = __float2bfloat16(wv);
    __nv_bfloat16 val = (k < 128) ? hi
                      : __float2bfloat16(wv - __bfloat162float(hi));
    unsigned short u; memcpy(&u, &val, 2);
    *dst = u;
}

#define AS 130    // A row stride in bf16 (65 words; 65 mod 32 = 1)
#define BS 200    // B row stride in bf16 (100 words; 16B-aligned rows)

// ---------------------------------------------------------------------------
// Kernel 1 (v10, mma): offset/mod conv as 9-tap GEMM, channel-last A fill.
// ---------------------------------------------------------------------------
__global__ void __launch_bounds__(128, 4) k_offconv_mma(
    const float* __restrict__ ob, const float* __restrict__ mb)
{
    extern __shared__ unsigned short sm[];
    unsigned short* Asm = sm;                 // 128*130*2 = 33280 B
    unsigned short* Bsm = sm + 128 * AS;      // 32*200*2  = 12800 B

    const int tid = threadIdx.x;
    const int wid = tid >> 5;
    const int lane = tid & 31;
    const int g = lane >> 2;
    const int q = lane & 3;

    const int p = blockIdx.x * 128 + tid;
    const int b = p / HW, r = p % HW;
    const int h = r / WW, w = r % WW;
    const float* xTb = g_xT + (size_t)b * HW * CC;

    float acc[2][4][4];
    #pragma unroll
    for (int mt = 0; mt < 2; mt++)
        #pragma unroll
        for (int nt = 0; nt < 4; nt++)
            #pragma unroll
            for (int e = 0; e < 4; e++) acc[mt][nt][e] = 0.f;

    #pragma unroll 1
    for (int n = 0; n < NN; n++) {
        // ---- B tile: 32 rows x 192 bf16 = 768 uint4, 6 per thread ----
        {
            const uint4* src = (const uint4*)(g_Bw2 + n * 32 * 192);
            #pragma unroll
            for (int j = 0; j < 6; j++) {
                int i = tid + 128 * j;
                int row = i / 24, c4 = i % 24;
                ((uint4*)(Bsm + row * BS))[c4] = __ldg(src + i);
            }
        }

        // ---- A fill: one contiguous 64-ch row (16 LDG.128), hi/lo split ----
        int dh = n / 3 - 1, dw = n % 3 - 1;
        int ih = h + dh, iw = w + dw;
        int off = ((unsigned)ih < HH && (unsigned)iw < WW) ? ih * WW + iw : -1;
        uint32_t* arow = (uint32_t*)(Asm + tid * AS);
        if (off >= 0) {
            const float4* xs4 = (const float4*)(xTb + (size_t)off * CC);
            #pragma unroll
            for (int j = 0; j < 16; j++) {
                float4 v = __ldg(xs4 + j);
                uint32_t hp0, lp0, hp1, lp1;
                split2(v.x, v.y, hp0, lp0);
                split2(v.z, v.w, hp1, lp1);
                arow[2 * j]     = hp0;
                arow[2 * j + 1] = hp1;
                arow[32 + 2 * j]     = lp0;
                arow[32 + 2 * j + 1] = lp1;
            }
        } else {
            #pragma unroll
            for (int j = 0; j < 64; j++) arow[j] = 0u;
        }
        __syncthreads();

        // ---- 12 K-steps of m16n8k16, 4 n-tiles ----
        #pragma unroll
        for (int s = 0; s < 12; s++) {
            const int acol = (s < 8) ? s * 16 : (s - 8) * 16;
            const int bk = s * 16;
            uint32_t a[2][4];
            #pragma unroll
            for (int mt = 0; mt < 2; mt++) {
                int r0 = wid * 32 + mt * 16 + g;
                const unsigned short* A0 = Asm + r0 * AS + acol + q * 2;
                const unsigned short* A1 = A0 + 8 * AS;
                a[mt][0] = *(const uint32_t*)A0;
                a[mt][1] = *(const uint32_t*)A1;
                a[mt][2] = *(const uint32_t*)(A0 + 8);
                a[mt][3] = *(const uint32_t*)(A1 + 8);
            }
            #pragma unroll
            for (int nt = 0; nt < 4; nt++) {
                const unsigned short* Bp = Bsm + (nt * 8 + g) * BS + bk + q * 2;
                uint32_t b0 = *(const uint32_t*)Bp;
                uint32_t b1 = *(const uint32_t*)(Bp + 8);
                mma_bf16(acc[0][nt], a[0], b0, b1);
                mma_bf16(acc[1][nt], a[1], b0, b1);
            }
        }
        __syncthreads();
    }

    // ---- epilogue -> g_scr[oc][pixel] (+bias), oc < 27 ----
    #pragma unroll
    for (int mt = 0; mt < 2; mt++) {
        int prow = blockIdx.x * 128 + wid * 32 + mt * 16 + g;
        #pragma unroll
        for (int nt = 0; nt < 4; nt++) {
            int oc = nt * 8 + q * 2;
            if (oc < 27) {
                float bias = (oc < 18) ? ob[oc] : mb[oc - 18];
                g_scr[(size_t)oc * PIXELS + prow]     = acc[mt][nt][0] + bias;
                g_scr[(size_t)oc * PIXELS + prow + 8] = acc[mt][nt][2] + bias;
            }
            if (oc + 1 < 27) {
                float bias = (oc + 1 < 18) ? ob[oc + 1] : mb[oc - 17];
                g_scr[(size_t)(oc + 1) * PIXELS + prow]     = acc[mt][nt][1] + bias;
                g_scr[(size_t)(oc + 1) * PIXELS + prow + 8] = acc[mt][nt][3] + bias;
            }
        }
    }
}

// ---------------------------------------------------------------------------
// Kernel 2 (v10, mma.sync bf16): deformable sampling + contraction,
// channel-last gathers: 4 corners x 16 LDG.128 per tap.
// ---------------------------------------------------------------------------
__global__ void __launch_bounds__(128, 3) k_deform_mma(
    const float* __restrict__ cb, float* __restrict__ out)
{
    extern __shared__ unsigned short sm[];
    unsigned short* Asm = sm;                 // 128*130*2 = 33280 B
    unsigned short* Bsm = sm + 128 * AS;      // 64*200*2  = 25600 B

    const int tid = threadIdx.x;
    const int wid = tid >> 5;
    const int lane = tid & 31;
    const int g = lane >> 2;
    const int q = lane & 3;

    const int p = blockIdx.x * 128 + tid;
    const int b = p / HW, r = p % HW;
    const int h = r / WW, w = r % WW;
    const float* xTb = g_xT + (size_t)b * HW * CC;

    float acc[2][8][4];
    #pragma unroll
    for (int mt = 0; mt < 2; mt++)
        #pragma unroll
        for (int nt = 0; nt < 8; nt++)
            #pragma unroll
            for (int e = 0; e < 4; e++) acc[mt][nt][e] = 0.f;

    #pragma unroll 1
    for (int n = 0; n < NN; n++) {
        // ---- B tile: 64 rows x 192 bf16 = 1536 uint4, 12 per thread ----
        {
            const uint4* src = (const uint4*)(g_Bw + n * 64 * 192);
            #pragma unroll
            for (int j = 0; j < 12; j++) {
                int i = tid + 128 * j;
                int row = i / 24, c4 = i % 24;
                ((uint4*)(Bsm + row * BS))[c4] = __ldg(src + i);
            }
        }

        // ---- sampling coordinates ----
        float offx = g_scr[n * PIXELS + p];
        float offy = g_scr[(9 + n) * PIXELS + p];
        float mraw = g_scr[(18 + n) * PIXELS + p];
        float m = 1.f / (1.f + __expf(-mraw));

        float px = offx + (float)(h + 1) + (float)(n / 3 - 1);
        float py = offy + (float)(w + 1) + (float)(n % 3 - 1);

        float flx = floorf(px), fly = floorf(py);
        int tlx = max(min((int)flx, 97), 0);
        int brx = max(min((int)flx + 1, 97), 0);
        int tly = max(min((int)fly, 97), 0);
        int bry = max(min((int)fly + 1, 97), 0);
        float pcx = fminf(fmaxf(px, 0.f), 97.f);
        float pcy = fminf(fmaxf(py, 0.f), 97.f);

        float axt = 1.f + ((float)tlx - pcx);
        float axb = 1.f - ((float)brx - pcx);
        float ayt = 1.f + ((float)tly - pcy);
        float ayb = 1.f - ((float)bry - pcy);

        float c_tl = axt * ayt * m;
        float c_tr = axt * ayb * m;
        float c_bl = axb * ayt * m;
        float c_br = axb * ayb * m;

        bool vtx = (tlx >= 1 && tlx <= 96);
        bool vbx = (brx >= 1 && brx <= 96);
        bool vty = (tly >= 1 && tly <= 96);
        bool vby = (bry >= 1 && bry <= 96);

        int a_tl = (tlx - 1) * WW + (tly - 1);
        int a_tr = (tlx - 1) * WW + (bry - 1);
        int a_bl = (brx - 1) * WW + (tly - 1);
        int a_br = (brx - 1) * WW + (bry - 1);
        if (!(vtx && vty)) { c_tl = 0.f; a_tl = 0; }
        if (!(vtx && vby)) { c_tr = 0.f; a_tr = 0; }
        if (!(vbx && vty)) { c_bl = 0.f; a_bl = 0; }
        if (!(vbx && vby)) { c_br = 0.f; a_br = 0; }

        // ---- gather 4 corner rows (channel-last), combine, split hi/lo ----
        const float4* ptl  = (const float4*)(xTb + (size_t)a_tl * CC);
        const float4* ptr_ = (const float4*)(xTb + (size_t)a_tr * CC);
        const float4* pbl  = (const float4*)(xTb + (size_t)a_bl * CC);
        const float4* pbr  = (const float4*)(xTb + (size_t)a_br * CC);
        uint32_t* arow = (uint32_t*)(Asm + tid * AS);
        #pragma unroll 4
        for (int j = 0; j < 16; j++) {
            float4 tl = __ldg(ptl + j);
            float4 tr = __ldg(ptr_ + j);
            float4 bl = __ldg(pbl + j);
            float4 br = __ldg(pbr + j);
            float v0 = c_tl * tl.x + c_tr * tr.x + c_bl * bl.x + c_br * br.x;
            float v1 = c_tl * tl.y + c_tr * tr.y + c_bl * bl.y + c_br * br.y;
            float v2 = c_tl * tl.z + c_tr * tr.z + c_bl * bl.z + c_br * br.z;
            float v3 = c_tl * tl.w + c_tr * tr.w + c_bl * bl.w + c_br * br.w;
            uint32_t hp0, lp0, hp1, lp1;
            split2(v0, v1, hp0, lp0);
            split2(v2, v3, hp1, lp1);
            arow[2 * j]     = hp0;
            arow[2 * j + 1] = hp1;
            arow[32 + 2 * j]     = lp0;
            arow[32 + 2 * j + 1] = lp1;
        }
        __syncthreads();

        // ---- 12 K-steps of m16n8k16, 8 n-tiles ----
        #pragma unroll
        for (int s = 0; s < 12; s++) {
            const int acol = (s < 8) ? s * 16 : (s - 8) * 16;
            const int bk = s * 16;
            uint32_t a[2][4];
            #pragma unroll
            for (int mt = 0; mt < 2; mt++) {
                int r0 = wid * 32 + mt * 16 + g;
                const unsigned short* A0 = Asm + r0 * AS + acol + q * 2;
                const unsigned short* A1 = A0 + 8 * AS;
                a[mt][0] = *(const uint32_t*)A0;
                a[mt][1] = *(const uint32_t*)A1;
                a[mt][2] = *(const uint32_t*)(A0 + 8);
                a[mt][3] = *(const uint32_t*)(A1 + 8);
            }
            #pragma unroll
            for (int nt = 0; nt < 8; nt++) {
                const unsigned short* Bp = Bsm + (nt * 8 + g) * BS + bk + q * 2;
                uint32_t b0 = *(const uint32_t*)Bp;
                uint32_t b1 = *(const uint32_t*)(Bp + 8);
                mma_bf16(acc[0][nt], a[0], b0, b1);
                mma_bf16(acc[1][nt], a[1], b0, b1);
            }
        }
        __syncthreads();
    }

    // ---- epilogue ----
    #pragma unroll
    for (int mt = 0; mt < 2; mt++) {
        int prow = blockIdx.x * 128 + wid * 32 + mt * 16 + g;
        int pb0 = prow / HW,       pr0 = prow % HW;
        int pb1 = (prow + 8) / HW, pr1 = (prow + 8) % HW;
        float* o0 = out + (size_t)pb0 * OO * HW + pr0;
        float* o1 = out + (size_t)pb1 * OO * HW + pr1;
        #pragma unroll
        for (int nt = 0; nt < 8; nt++) {
            int oc = nt * 8 + q * 2;
            float bb0 = cb[oc], bb1 = cb[oc + 1];
            o0[(size_t)oc * HW]       = acc[mt][nt][0] + bb0;
            o0[(size_t)(oc + 1) * HW] = acc[mt][nt][1] + bb1;
            o1[(size_t)oc * HW]       = acc[mt][nt][2] + bb0;
            o1[(size_t)(oc + 1) * HW] = acc[mt][nt][3] + bb1;
        }
    }
}

extern "C" void kernel_launch(void* const* d_in, const int* in_sizes, int n_in,
                              void* d_out, int out_size) {
    const float* x  = (const float*)d_in[0];
    const float* ow = (const float*)d_in[1];
    const float* ob = (const float*)d_in[2];
    const float* mw = (const float*)d_in[3];
    const float* mb = (const float*)d_in[4];
    const float* cw = (const float*)d_in[5];
    const float* cb = (const float*)d_in[6];
    float* out = (float*)d_out;

    const int smem1 = (128 * AS + 32 * BS) * 2;   // 46080 B
    const int smem2 = (128 * AS + 64 * BS) * 2;   // 58880 B
    cudaFuncSetAttribute(k_offconv_mma, cudaFuncAttributeMaxDynamicSharedMemorySize, smem1);
    cudaFuncSetAttribute(k_deform_mma,  cudaFuncAttributeMaxDynamicSharedMemorySize, smem2);

    dim3 gx(HW / 32, BB);
    k_prepx<<<gx, 256>>>(x);
    k_prepw<<<648, 256>>>(cw, ow, mw);
    k_offconv_mma<<<PIXELS / 128, 128, smem1>>>(ob, mb);
    k_deform_mma<<<PIXELS / 128, 128, smem2>>>(cb, out);
}

// round 11
// speedup vs baseline: 1.8368x; 1.8368x over previous
#include <cuda_runtime.h>
#include <cuda_bf16.h>
#include <math.h>
#include <cstdint>

#define BB 8
#define CC 64
#define OO 64
#define HH 96
#define WW 96
#define NN 9
#define HW (HH*WW)            // 9216
#define PIXELS (BB*HH*WW)     // 73728
#define SCR_CH 27

// offset (18) + modulation-raw (9) planes, layout [ch][pixel], bias included
__device__ float g_scr[SCR_CH * PIXELS];
// prepped B for deform: [tap][o(64)][k(128)] bf16, k = [whi(64) | wlo(64)]
__device__ __align__(16) unsigned short g_Bw[NN * 64 * 128];
// prepped B for offconv: [tap][o(32, 27 used)][k(192)] bf16, k = [whi|whi|wlo]
__device__ __align__(16) unsigned short g_Bw2[NN * 32 * 192];

// bf16 mma: D += A(16x16 row) * B(16x8 col)
__device__ __forceinline__ void mma_bf16(float* d, const uint32_t* a,
                                         uint32_t b0, uint32_t b1) {
    asm volatile(
        "mma.sync.aligned.m16n8k16.row.col.f32.bf16.bf16.f32 "
        "{%0,%1,%2,%3}, {%4,%5,%6,%7}, {%8,%9}, {%0,%1,%2,%3};"
        : "+f"(d[0]), "+f"(d[1]), "+f"(d[2]), "+f"(d[3])
        : "r"(a[0]), "r"(a[1]), "r"(a[2]), "r"(a[3]), "r"(b0), "r"(b1));
}

__device__ __forceinline__ void ldmatrix_x4(uint32_t* r, uint32_t addr) {
    asm volatile(
        "ldmatrix.sync.aligned.m8n8.x4.shared.b16 {%0,%1,%2,%3}, [%4];"
        : "=r"(r[0]), "=r"(r[1]), "=r"(r[2]), "=r"(r[3]) : "r"(addr));
}
__device__ __forceinline__ void ldmatrix_x2(uint32_t& r0, uint32_t& r1,
                                            uint32_t addr) {
    asm volatile(
        "ldmatrix.sync.aligned.m8n8.x2.shared.b16 {%0,%1}, [%2];"
        : "=r"(r0), "=r"(r1) : "r"(addr));
}
__device__ __forceinline__ uint32_t smem_u32(const void* p) {
    uint32_t a;
    asm("{ .reg .u64 t; cvta.to.shared.u64 t, %1; cvt.u32.u64 %0, t; }"
        : "=r"(a) : "l"(p));
    return a;
}

// split two fp32 into packed bf16 hi + bf16 lo-residual
__device__ __forceinline__ void split2(float v0, float v1,
                                       uint32_t& hp, uint32_t& lp) {
    asm("cvt.rn.satfinite.bf16x2.f32 %0, %1, %2;" : "=r"(hp) : "f"(v1), "f"(v0));
    float h0 = __uint_as_float(hp << 16);
    float h1 = __uint_as_float(hp & 0xffff0000u);
    float l0 = v0 - h0, l1 = v1 - h1;
    asm("cvt.rn.satfinite.bf16x2.f32 %0, %1, %2;" : "=r"(lp) : "f"(l1), "f"(l0));
}

// ---------------------------------------------------------------------------
// Kernel P: build both B images (hi/lo split).
//   i <  73728 : deform B (128-wide: [whi|wlo]), w = cw[o][c][tap]
//   i >= 73728 : offconv B (192-wide: [whi|whi|wlo]), ow/mw
// ---------------------------------------------------------------------------
__global__ void __launch_bounds__(256) k_prepw(
    const float* __restrict__ cw,
    const float* __restrict__ ow, const float* __restrict__ mw)
{
    int i = blockIdx.x * 256 + threadIdx.x;     // 504*256 = 129024
    if (i < NN * 64 * 128) {
        int n = i / (64 * 128);
        int rr = i % (64 * 128);
        int o = rr / 128;
        int k = rr % 128;
        int c = k & 63;
        float wv = cw[(o * CC + c) * NN + n];
        __nv_bfloat16 hi = __float2bfloat16(wv);
        __nv_bfloat16 val = (k < 64) ? hi
                          : __float2bfloat16(wv - __bfloat162float(hi));
        unsigned short u; memcpy(&u, &val, 2);
        g_Bw[i] = u;
    } else {
        int j = i - NN * 64 * 128;              // 9*32*192 = 55296
        int n = j / (32 * 192);
        int rr = j % (32 * 192);
        int o = rr / 192;
        int k = rr % 192;
        int c = k & 63;
        float wv = (o < 18) ? ow[(o * CC + c) * 9 + n]
                 : (o < 27) ? mw[((o - 18) * CC + c) * 9 + n] : 0.f;
        __nv_bfloat16 hi = __float2bfloat16(wv);
        __nv_bfloat16 val = (k < 128) ? hi
                          : __float2bfloat16(wv - __bfloat162float(hi));
        unsigned short u; memcpy(&u, &val, 2);
        g_Bw2[j] = u;
    }
}

#define AS 130    // offconv A row stride (bf16)
#define BS 200    // offconv B row stride (bf16)
#define AS2 136   // deform A row stride (68 words; 68 mod 32 = 4 -> ldmatrix ok)
#define BS2 136   // deform B row stride

// ---------------------------------------------------------------------------
// Kernel 1 (round-9 verbatim, PASSING): offset/mod conv as 9-tap GEMM.
// ---------------------------------------------------------------------------
__global__ void __launch_bounds__(128, 4) k_offconv_mma(
    const float* __restrict__ x,
    const float* __restrict__ ob, const float* __restrict__ mb)
{
    extern __shared__ unsigned short sm[];
    unsigned short* Asm = sm;                 // 128*130*2 = 33280 B
    unsigned short* Bsm = sm + 128 * AS;      // 32*200*2  = 12800 B

    const int tid = threadIdx.x;
    const int wid = tid >> 5;
    const int lane = tid & 31;
    const int g = lane >> 2;
    const int q = lane & 3;

    const int p = blockIdx.x * 128 + tid;
    const int b = p / HW, r = p % HW;
    const int h = r / WW, w = r % WW;
    const float* xg = x + (size_t)b * CC * HW;

    float acc[2][4][4];
    #pragma unroll
    for (int mt = 0; mt < 2; mt++)
        #pragma unroll
        for (int nt = 0; nt < 4; nt++)
            #pragma unroll
            for (int e = 0; e < 4; e++) acc[mt][nt][e] = 0.f;

    #pragma unroll 1
    for (int n = 0; n < NN; n++) {
        {
            const uint4* src = (const uint4*)(g_Bw2 + n * 32 * 192);
            #pragma unroll
            for (int j = 0; j < 6; j++) {
                int i = tid + 128 * j;
                int row = i / 24, c4 = i % 24;
                ((uint4*)(Bsm + row * BS))[c4] = __ldg(src + i);
            }
        }

        int dh = n / 3 - 1, dw = n % 3 - 1;
        int ih = h + dh, iw = w + dw;
        int off = ((unsigned)ih < HH && (unsigned)iw < WW) ? ih * WW + iw : -1;
        const float* xs = xg + off;
        uint32_t* arow = (uint32_t*)(Asm + tid * AS);
        #pragma unroll 4
        for (int j = 0; j < 32; j++) {
            float v0 = 0.f, v1 = 0.f;
            if (off >= 0) {
                v0 = __ldg(xs + (size_t)(2 * j) * HW);
                v1 = __ldg(xs + (size_t)(2 * j + 1) * HW);
            }
            uint32_t hp, lp;
            split2(v0, v1, hp, lp);
            arow[j] = hp;
            arow[32 + j] = lp;
        }
        __syncthreads();

        #pragma unroll
        for (int s = 0; s < 12; s++) {
            const int acol = (s < 8) ? s * 16 : (s - 8) * 16;
            const int bk = s * 16;
            uint32_t a[2][4];
            #pragma unroll
            for (int mt = 0; mt < 2; mt++) {
                int r0 = wid * 32 + mt * 16 + g;
                const unsigned short* A0 = Asm + r0 * AS + acol + q * 2;
                const unsigned short* A1 = A0 + 8 * AS;
                a[mt][0] = *(const uint32_t*)A0;
                a[mt][1] = *(const uint32_t*)A1;
                a[mt][2] = *(const uint32_t*)(A0 + 8);
                a[mt][3] = *(const uint32_t*)(A1 + 8);
            }
            #pragma unroll
            for (int nt = 0; nt < 4; nt++) {
                const unsigned short* Bp = Bsm + (nt * 8 + g) * BS + bk + q * 2;
                uint32_t b0 = *(const uint32_t*)Bp;
                uint32_t b1 = *(const uint32_t*)(Bp + 8);
                mma_bf16(acc[0][nt], a[0], b0, b1);
                mma_bf16(acc[1][nt], a[1], b0, b1);
            }
        }
        __syncthreads();
    }

    #pragma unroll
    for (int mt = 0; mt < 2; mt++) {
        int prow = blockIdx.x * 128 + wid * 32 + mt * 16 + g;
        #pragma unroll
        for (int nt = 0; nt < 4; nt++) {
            int oc = nt * 8 + q * 2;
            if (oc < 27) {
                float bias = (oc < 18) ? ob[oc] : mb[oc - 18];
                g_scr[(size_t)oc * PIXELS + prow]     = acc[mt][nt][0] + bias;
                g_scr[(size_t)oc * PIXELS + prow + 8] = acc[mt][nt][2] + bias;
            }
            if (oc + 1 < 27) {
                float bias = (oc + 1 < 18) ? ob[oc + 1] : mb[oc - 17];
                g_scr[(size_t)(oc + 1) * PIXELS + prow]     = acc[mt][nt][1] + bias;
                g_scr[(size_t)(oc + 1) * PIXELS + prow + 8] = acc[mt][nt][3] + bias;
            }
        }
    }
}

// ---------------------------------------------------------------------------
// Kernel 2 (v11): deform GEMM, NCHW coalesced gather (reverted), plus:
//  - 256 thr CTA, 2 threads/pixel (each gathers 32 channels): acc = 32 regs
//    -> launch_bounds(256,2) = 16 warps/SM
//  - warp w: rows (w&3)*32..+32, outputs (w>>2)*32..+32
//  - A stride 68 words (bank-quad aligned) + ldmatrix fragment loads
//  - B deduped to 128 cols ([whi|wlo]); step remap ka/kb
// ---------------------------------------------------------------------------
__global__ void __launch_bounds__(256, 2) k_deform_mma(
    const float* __restrict__ x, const float* __restrict__ cb,
    float* __restrict__ out)
{
    extern __shared__ unsigned short sm[];
    unsigned short* Asm = sm;                 // 128*136*2 = 34816 B
    unsigned short* Bsm = sm + 128 * AS2;     // 64*136*2  = 17408 B

    const int tid = threadIdx.x;
    const int wid = tid >> 5;
    const int lane = tid & 31;
    const int g = lane >> 2;
    const int q = lane & 3;

    const int pxl = tid & 127;                // pixel index within CTA
    const int chalf = tid >> 7;               // channel half 0/1
    const int p = blockIdx.x * 128 + pxl;
    const int b = p / HW, r = p % HW;
    const int h = r / WW, w = r % WW;
    const float* xg = x + ((size_t)b * CC + chalf * 32) * HW;

    // ldmatrix lane addresses
    const uint32_t asm_b = smem_u32(Asm);
    const uint32_t bsm_b = smem_u32(Bsm);
    const int tA = lane >> 3, riA = lane & 7;
    const int rowsBase = (wid & 3) * 32;
    const int nhalf = wid >> 2;               // output half
    uint32_t aAddr[2];
    #pragma unroll
    for (int mt = 0; mt < 2; mt++) {
        int row = rowsBase + mt * 16 + (tA & 1) * 8 + riA;
        aAddr[mt] = asm_b + (uint32_t)(row * AS2 + (tA >> 1) * 8) * 2;
    }
    const int l16 = lane & 15;
    const int tB = l16 >> 3, riB = l16 & 7;
    uint32_t bAddr[4];
    #pragma unroll
    for (int nt = 0; nt < 4; nt++) {
        int row = (nhalf * 4 + nt) * 8 + riB;
        bAddr[nt] = bsm_b + (uint32_t)(row * BS2 + tB * 8) * 2;
    }

    float acc[2][4][4];
    #pragma unroll
    for (int mt = 0; mt < 2; mt++)
        #pragma unroll
        for (int nt = 0; nt < 4; nt++)
            #pragma unroll
            for (int e = 0; e < 4; e++) acc[mt][nt][e] = 0.f;

    #pragma unroll 1
    for (int n = 0; n < NN; n++) {
        // ---- B tile: 64 rows x 128 bf16 = 1024 uint4, 4 per thread ----
        {
            const uint4* src = (const uint4*)(g_Bw + n * 64 * 128);
            #pragma unroll
            for (int j = 0; j < 4; j++) {
                int i = tid + 256 * j;
                int row = i >> 4, c4 = i & 15;
                ((uint4*)(Bsm + row * BS2))[c4] = __ldg(src + i);
            }
        }

        // ---- sampling coordinates (both chalf threads recompute) ----
        float offx = g_scr[n * PIXELS + p];
        float offy = g_scr[(9 + n) * PIXELS + p];
        float mraw = g_scr[(18 + n) * PIXELS + p];
        float m = 1.f / (1.f + __expf(-mraw));

        float px = offx + (float)(h + 1) + (float)(n / 3 - 1);
        float py = offy + (float)(w + 1) + (float)(n % 3 - 1);

        float flx = floorf(px), fly = floorf(py);
        int tlx = max(min((int)flx, 97), 0);
        int brx = max(min((int)flx + 1, 97), 0);
        int tly = max(min((int)fly, 97), 0);
        int bry = max(min((int)fly + 1, 97), 0);
        float pcx = fminf(fmaxf(px, 0.f), 97.f);
        float pcy = fminf(fmaxf(py, 0.f), 97.f);

        float axt = 1.f + ((float)tlx - pcx);
        float axb = 1.f - ((float)brx - pcx);
        float ayt = 1.f + ((float)tly - pcy);
        float ayb = 1.f - ((float)bry - pcy);

        float c_tl = axt * ayt * m;
        float c_tr = axt * ayb * m;
        float c_bl = axb * ayt * m;
        float c_br = axb * ayb * m;

        bool vtx = (tlx >= 1 && tlx <= 96);
        bool vbx = (brx >= 1 && brx <= 96);
        bool vty = (tly >= 1 && tly <= 96);
        bool vby = (bry >= 1 && bry <= 96);

        int a_tl = (tlx - 1) * WW + (tly - 1);
        int a_tr = (tlx - 1) * WW + (bry - 1);
        int a_bl = (brx - 1) * WW + (tly - 1);
        int a_br = (brx - 1) * WW + (bry - 1);
        if (!(vtx && vty)) { c_tl = 0.f; a_tl = 0; }
        if (!(vtx && vby)) { c_tr = 0.f; a_tr = 0; }
        if (!(vbx && vty)) { c_bl = 0.f; a_bl = 0; }
        if (!(vbx && vby)) { c_br = 0.f; a_br = 0; }

        // ---- gather 32 channels (NCHW, warp-coalesced), split hi/lo ----
        // hi words [chalf*16, +16), lo words [32+chalf*16, +16) of row pxl
        uint2* arow = (uint2*)(Asm + pxl * AS2);
        #pragma unroll 2
        for (int it = 0; it < 8; it++) {
            const float* x0 = xg + (size_t)(4 * it) * HW;
            float t0 = c_tl * __ldg(x0 + a_tl) + c_tr * __ldg(x0 + a_tr)
                     + c_bl * __ldg(x0 + a_bl) + c_br * __ldg(x0 + a_br);
            const float* x1 = x0 + HW;
            float t1 = c_tl * __ldg(x1 + a_tl) + c_tr * __ldg(x1 + a_tr)
                     + c_bl * __ldg(x1 + a_bl) + c_br * __ldg(x1 + a_br);
            const float* x2 = x1 + HW;
            float t2 = c_tl * __ldg(x2 + a_tl) + c_tr * __ldg(x2 + a_tr)
                     + c_bl * __ldg(x2 + a_bl) + c_br * __ldg(x2 + a_br);
            const float* x3 = x2 + HW;
            float t3 = c_tl * __ldg(x3 + a_tl) + c_tr * __ldg(x3 + a_tr)
                     + c_bl * __ldg(x3 + a_bl) + c_br * __ldg(x3 + a_br);
            uint32_t hp0, lp0, hp1, lp1;
            split2(t0, t1, hp0, lp0);
            split2(t2, t3, hp1, lp1);
            arow[chalf * 8 + it]      = make_uint2(hp0, hp1);
            arow[16 + chalf * 8 + it] = make_uint2(lp0, lp1);
        }
        __syncthreads();

        // ---- 12 K-steps of m16n8k16 ----
        #pragma unroll
        for (int s = 0; s < 12; s++) {
            const int s3 = (s & 3) * 16;
            const int ka = s3 + ((s >= 4 && s < 8) ? 64 : 0);
            const int kb = s3 + ((s >= 8) ? 64 : 0);
            uint32_t a[2][4];
            ldmatrix_x4(a[0], aAddr[0] + ka * 2);
            ldmatrix_x4(a[1], aAddr[1] + ka * 2);
            #pragma unroll
            for (int nt = 0; nt < 4; nt++) {
                uint32_t b0, b1;
                ldmatrix_x2(b0, b1, bAddr[nt] + kb * 2);
                mma_bf16(acc[0][nt], a[0], b0, b1);
                mma_bf16(acc[1][nt], a[1], b0, b1);
            }
        }
        __syncthreads();
    }

    // ---- epilogue: rows = pixels, cols = (nhalf*32 + nt*8 + q*2) ----
    #pragma unroll
    for (int mt = 0; mt < 2; mt++) {
        int prow = blockIdx.x * 128 + rowsBase + mt * 16 + g;
        int pb0 = prow / HW,       pr0 = prow % HW;
        int pb1 = (prow + 8) / HW, pr1 = (prow + 8) % HW;
        float* o0 = out + (size_t)pb0 * OO * HW + pr0;
        float* o1 = out + (size_t)pb1 * OO * HW + pr1;
        #pragma unroll
        for (int nt = 0; nt < 4; nt++) {
            int oc = nhalf * 32 + nt * 8 + q * 2;
            float bb0 = cb[oc], bb1 = cb[oc + 1];
            o0[(size_t)oc * HW]       = acc[mt][nt][0] + bb0;
            o0[(size_t)(oc + 1) * HW] = acc[mt][nt][1] + bb1;
            o1[(size_t)oc * HW]       = acc[mt][nt][2] + bb0;
            o1[(size_t)(oc + 1) * HW] = acc[mt][nt][3] + bb1;
        }
    }
}

extern "C" void kernel_launch(void* const* d_in, const int* in_sizes, int n_in,
                              void* d_out, int out_size) {
    const float* x  = (const float*)d_in[0];
    const float* ow = (const float*)d_in[1];
    const float* ob = (const float*)d_in[2];
    const float* mw = (const float*)d_in[3];
    const float* mb = (const float*)d_in[4];
    const float* cw = (const float*)d_in[5];
    const float* cb = (const float*)d_in[6];
    float* out = (float*)d_out;

    const int smem1 = (128 * AS + 32 * BS) * 2;    // 46080 B
    const int smem2 = (128 * AS2 + 64 * BS2) * 2;  // 52224 B
    cudaFuncSetAttribute(k_offconv_mma, cudaFuncAttributeMaxDynamicSharedMemorySize, smem1);
    cudaFuncSetAttribute(k_deform_mma,  cudaFuncAttributeMaxDynamicSharedMemorySize, smem2);

    k_prepw<<<504, 256>>>(cw, ow, mw);
    k_offconv_mma<<<PIXELS / 128, 128, smem1>>>(x, ob, mb);
    k_deform_mma<<<PIXELS / 128, 256, smem2>>>(x, cb, out);
}

// round 12
// speedup vs baseline: 1.9947x; 1.0860x over previous
#include <cuda_runtime.h>
#include <cuda_bf16.h>
#include <math.h>
#include <cstdint>

#define BB 8
#define CC 64
#define OO 64
#define HH 96
#define WW 96
#define NN 9
#define HW (HH*WW)            // 9216
#define PIXELS (BB*HH*WW)     // 73728
#define SCR_CH 27

// offset (18) + modulation-raw (9) planes, layout [ch][pixel], bias included
__device__ float g_scr[SCR_CH * PIXELS];
// prepped B for deform: [tap][o(64)][k(128)] bf16, k = [whi(64) | wlo(64)]
__device__ __align__(16) unsigned short g_Bw[NN * 64 * 128];
// prepped B for offconv: [tap][o(32, 27 used)][k(128)] bf16, k = [whi | wlo]
__device__ __align__(16) unsigned short g_Bw2[NN * 32 * 128];

// bf16 mma: D += A(16x16 row) * B(16x8 col)
__device__ __forceinline__ void mma_bf16(float* d, const uint32_t* a,
                                         uint32_t b0, uint32_t b1) {
    asm volatile(
        "mma.sync.aligned.m16n8k16.row.col.f32.bf16.bf16.f32 "
        "{%0,%1,%2,%3}, {%4,%5,%6,%7}, {%8,%9}, {%0,%1,%2,%3};"
        : "+f"(d[0]), "+f"(d[1]), "+f"(d[2]), "+f"(d[3])
        : "r"(a[0]), "r"(a[1]), "r"(a[2]), "r"(a[3]), "r"(b0), "r"(b1));
}

__device__ __forceinline__ void ldmatrix_x4(uint32_t* r, uint32_t addr) {
    asm volatile(
        "ldmatrix.sync.aligned.m8n8.x4.shared.b16 {%0,%1,%2,%3}, [%4];"
        : "=r"(r[0]), "=r"(r[1]), "=r"(r[2]), "=r"(r[3]) : "r"(addr));
}
__device__ __forceinline__ void ldmatrix_x2(uint32_t& r0, uint32_t& r1,
                                            uint32_t addr) {
    asm volatile(
        "ldmatrix.sync.aligned.m8n8.x2.shared.b16 {%0,%1}, [%2];"
        : "=r"(r0), "=r"(r1) : "r"(addr));
}
__device__ __forceinline__ uint32_t smem_u32(const void* p) {
    uint32_t a;
    asm("{ .reg .u64 t; cvta.to.shared.u64 t, %1; cvt.u32.u64 %0, t; }"
        : "=r"(a) : "l"(p));
    return a;
}

// split two fp32 into packed bf16 hi + bf16 lo-residual
__device__ __forceinline__ void split2(float v0, float v1,
                                       uint32_t& hp, uint32_t& lp) {
    asm("cvt.rn.satfinite.bf16x2.f32 %0, %1, %2;" : "=r"(hp) : "f"(v1), "f"(v0));
    float h0 = __uint_as_float(hp << 16);
    float h1 = __uint_as_float(hp & 0xffff0000u);
    float l0 = v0 - h0, l1 = v1 - h1;
    asm("cvt.rn.satfinite.bf16x2.f32 %0, %1, %2;" : "=r"(lp) : "f"(l1), "f"(l0));
}

// ---------------------------------------------------------------------------
// Kernel P: build both B images (hi/lo split, both 128-wide [whi|wlo]).
// ---------------------------------------------------------------------------
__global__ void __launch_bounds__(256) k_prepw(
    const float* __restrict__ cw,
    const float* __restrict__ ow, const float* __restrict__ mw)
{
    int i = blockIdx.x * 256 + threadIdx.x;     // 432*256 = 110592
    if (i < NN * 64 * 128) {
        int n = i / (64 * 128);
        int rr = i % (64 * 128);
        int o = rr / 128;
        int k = rr % 128;
        int c = k & 63;
        float wv = cw[(o * CC + c) * NN + n];
        __nv_bfloat16 hi = __float2bfloat16(wv);
        __nv_bfloat16 val = (k < 64) ? hi
                          : __float2bfloat16(wv - __bfloat162float(hi));
        unsigned short u; memcpy(&u, &val, 2);
        g_Bw[i] = u;
    } else {
        int j = i - NN * 64 * 128;              // 9*32*128 = 36864
        int n = j / (32 * 128);
        int rr = j % (32 * 128);
        int o = rr / 128;
        int k = rr % 128;
        int c = k & 63;
        float wv = (o < 18) ? ow[(o * CC + c) * 9 + n]
                 : (o < 27) ? mw[((o - 18) * CC + c) * 9 + n] : 0.f;
        __nv_bfloat16 hi = __float2bfloat16(wv);
        __nv_bfloat16 val = (k < 64) ? hi
                          : __float2bfloat16(wv - __bfloat162float(hi));
        unsigned short u; memcpy(&u, &val, 2);
        g_Bw2[j] = u;
    }
}

#define AS2 136   // A row stride (68 words; 68 mod 32 = 4 -> ldmatrix conflict-free)
#define BS2 136   // B row stride

// ---------------------------------------------------------------------------
// Kernel 1 (v12): offconv GEMM ported to the v11 structure.
// 256 thr, 2 thr/pixel; warp w: rows (w&3)*32, outputs (w>>2)*16.
// A stride 136 + ldmatrix; B deduped 32x128; 12 K-steps with ka/kb remap.
// ---------------------------------------------------------------------------
__global__ void __launch_bounds__(256, 2) k_offconv_mma(
    const float* __restrict__ x,
    const float* __restrict__ ob, const float* __restrict__ mb)
{
    extern __shared__ unsigned short sm[];
    unsigned short* Asm = sm;                 // 128*136*2 = 34816 B
    unsigned short* Bsm = sm + 128 * AS2;     // 32*136*2  = 8704 B

    const int tid = threadIdx.x;
    const int wid = tid >> 5;
    const int lane = tid & 31;
    const int g = lane >> 2;
    const int q = lane & 3;

    const int pxl = tid & 127;
    const int chalf = tid >> 7;
    const int p = blockIdx.x * 128 + pxl;
    const int b = p / HW, r = p % HW;
    const int h = r / WW, w = r % WW;
    const float* xg = x + ((size_t)b * CC + chalf * 32) * HW;

    const uint32_t asm_b = smem_u32(Asm);
    const uint32_t bsm_b = smem_u32(Bsm);
    const int tA = lane >> 3, riA = lane & 7;
    const int rowsBase = (wid & 3) * 32;
    const int nhalf = wid >> 2;               // output group of 16
    uint32_t aAddr[2];
    #pragma unroll
    for (int mt = 0; mt < 2; mt++) {
        int row = rowsBase + mt * 16 + (tA & 1) * 8 + riA;
        aAddr[mt] = asm_b + (uint32_t)(row * AS2 + (tA >> 1) * 8) * 2;
    }
    const int l16 = lane & 15;
    const int tB = l16 >> 3, riB = l16 & 7;
    uint32_t bAddr[2];
    #pragma unroll
    for (int nt = 0; nt < 2; nt++) {
        int row = (nhalf * 2 + nt) * 8 + riB;
        bAddr[nt] = bsm_b + (uint32_t)(row * BS2 + tB * 8) * 2;
    }

    float acc[2][2][4];
    #pragma unroll
    for (int mt = 0; mt < 2; mt++)
        #pragma unroll
        for (int nt = 0; nt < 2; nt++)
            #pragma unroll
            for (int e = 0; e < 4; e++) acc[mt][nt][e] = 0.f;

    #pragma unroll 1
    for (int n = 0; n < NN; n++) {
        // ---- B tile: 32 rows x 128 bf16 = 512 uint4, 2 per thread ----
        {
            const uint4* src = (const uint4*)(g_Bw2 + n * 32 * 128);
            #pragma unroll
            for (int j = 0; j < 2; j++) {
                int i = tid + 256 * j;
                int row = i >> 4, c4 = i & 15;
                ((uint4*)(Bsm + row * BS2))[c4] = __ldg(src + i);
            }
        }

        // ---- A fill: shifted-window coalesced loads, 32 ch/thread ----
        int dh = n / 3 - 1, dw = n % 3 - 1;
        int ih = h + dh, iw = w + dw;
        int off = ((unsigned)ih < HH && (unsigned)iw < WW) ? ih * WW + iw : -1;
        const float* xs = xg + off;
        uint2* arow = (uint2*)(Asm + pxl * AS2);
        if (off >= 0) {
            #pragma unroll 2
            for (int it = 0; it < 8; it++) {
                float t0 = __ldg(xs + (size_t)(4 * it) * HW);
                float t1 = __ldg(xs + (size_t)(4 * it + 1) * HW);
                float t2 = __ldg(xs + (size_t)(4 * it + 2) * HW);
                float t3 = __ldg(xs + (size_t)(4 * it + 3) * HW);
                uint32_t hp0, lp0, hp1, lp1;
                split2(t0, t1, hp0, lp0);
                split2(t2, t3, hp1, lp1);
                arow[chalf * 8 + it]      = make_uint2(hp0, hp1);
                arow[16 + chalf * 8 + it] = make_uint2(lp0, lp1);
            }
        } else {
            #pragma unroll
            for (int it = 0; it < 8; it++) {
                arow[chalf * 8 + it]      = make_uint2(0u, 0u);
                arow[16 + chalf * 8 + it] = make_uint2(0u, 0u);
            }
        }
        __syncthreads();

        // ---- 12 K-steps of m16n8k16 ----
        #pragma unroll
        for (int s = 0; s < 12; s++) {
            const int s3 = (s & 3) * 16;
            const int ka = s3 + ((s >= 4 && s < 8) ? 64 : 0);
            const int kb = s3 + ((s >= 8) ? 64 : 0);
            uint32_t a[2][4];
            ldmatrix_x4(a[0], aAddr[0] + ka * 2);
            ldmatrix_x4(a[1], aAddr[1] + ka * 2);
            #pragma unroll
            for (int nt = 0; nt < 2; nt++) {
                uint32_t b0, b1;
                ldmatrix_x2(b0, b1, bAddr[nt] + kb * 2);
                mma_bf16(acc[0][nt], a[0], b0, b1);
                mma_bf16(acc[1][nt], a[1], b0, b1);
            }
        }
        __syncthreads();
    }

    // ---- epilogue -> g_scr[oc][pixel] (+bias), oc < 27 ----
    #pragma unroll
    for (int mt = 0; mt < 2; mt++) {
        int prow = blockIdx.x * 128 + rowsBase + mt * 16 + g;
        #pragma unroll
        for (int nt = 0; nt < 2; nt++) {
            int oc = nhalf * 16 + nt * 8 + q * 2;
            if (oc < 27) {
                float bias = (oc < 18) ? ob[oc] : mb[oc - 18];
                g_scr[(size_t)oc * PIXELS + prow]     = acc[mt][nt][0] + bias;
                g_scr[(size_t)oc * PIXELS + prow + 8] = acc[mt][nt][2] + bias;
            }
            if (oc + 1 < 27) {
                float bias = (oc + 1 < 18) ? ob[oc + 1] : mb[oc - 17];
                g_scr[(size_t)(oc + 1) * PIXELS + prow]     = acc[mt][nt][1] + bias;
                g_scr[(size_t)(oc + 1) * PIXELS + prow + 8] = acc[mt][nt][3] + bias;
            }
        }
    }
}

// ---------------------------------------------------------------------------
// Kernel 2 (v11 verbatim, PASSING): deform GEMM.
// ---------------------------------------------------------------------------
__global__ void __launch_bounds__(256, 2) k_deform_mma(
    const float* __restrict__ x, const float* __restrict__ cb,
    float* __restrict__ out)
{
    extern __shared__ unsigned short sm[];
    unsigned short* Asm = sm;                 // 128*136*2 = 34816 B
    unsigned short* Bsm = sm + 128 * AS2;     // 64*136*2  = 17408 B

    const int tid = threadIdx.x;
    const int wid = tid >> 5;
    const int lane = tid & 31;
    const int g = lane >> 2;
    const int q = lane & 3;

    const int pxl = tid & 127;
    const int chalf = tid >> 7;
    const int p = blockIdx.x * 128 + pxl;
    const int b = p / HW, r = p % HW;
    const int h = r / WW, w = r % WW;
    const float* xg = x + ((size_t)b * CC + chalf * 32) * HW;

    const uint32_t asm_b = smem_u32(Asm);
    const uint32_t bsm_b = smem_u32(Bsm);
    const int tA = lane >> 3, riA = lane & 7;
    const int rowsBase = (wid & 3) * 32;
    const int nhalf = wid >> 2;
    uint32_t aAddr[2];
    #pragma unroll
    for (int mt = 0; mt < 2; mt++) {
        int row = rowsBase + mt * 16 + (tA & 1) * 8 + riA;
        aAddr[mt] = asm_b + (uint32_t)(row * AS2 + (tA >> 1) * 8) * 2;
    }
    const int l16 = lane & 15;
    const int tB = l16 >> 3, riB = l16 & 7;
    uint32_t bAddr[4];
    #pragma unroll
    for (int nt = 0; nt < 4; nt++) {
        int row = (nhalf * 4 + nt) * 8 + riB;
        bAddr[nt] = bsm_b + (uint32_t)(row * BS2 + tB * 8) * 2;
    }

    float acc[2][4][4];
    #pragma unroll
    for (int mt = 0; mt < 2; mt++)
        #pragma unroll
        for (int nt = 0; nt < 4; nt++)
            #pragma unroll
            for (int e = 0; e < 4; e++) acc[mt][nt][e] = 0.f;

    #pragma unroll 1
    for (int n = 0; n < NN; n++) {
        // ---- B tile: 64 rows x 128 bf16 = 1024 uint4, 4 per thread ----
        {
            const uint4* src = (const uint4*)(g_Bw + n * 64 * 128);
            #pragma unroll
            for (int j = 0; j < 4; j++) {
                int i = tid + 256 * j;
                int row = i >> 4, c4 = i & 15;
                ((uint4*)(Bsm + row * BS2))[c4] = __ldg(src + i);
            }
        }

        // ---- sampling coordinates ----
        float offx = g_scr[n * PIXELS + p];
        float offy = g_scr[(9 + n) * PIXELS + p];
        float mraw = g_scr[(18 + n) * PIXELS + p];
        float m = 1.f / (1.f + __expf(-mraw));

        float px = offx + (float)(h + 1) + (float)(n / 3 - 1);
        float py = offy + (float)(w + 1) + (float)(n % 3 - 1);

        float flx = floorf(px), fly = floorf(py);
        int tlx = max(min((int)flx, 97), 0);
        int brx = max(min((int)flx + 1, 97), 0);
        int tly = max(min((int)fly, 97), 0);
        int bry = max(min((int)fly + 1, 97), 0);
        float pcx = fminf(fmaxf(px, 0.f), 97.f);
        float pcy = fminf(fmaxf(py, 0.f), 97.f);

        float axt = 1.f + ((float)tlx - pcx);
        float axb = 1.f - ((float)brx - pcx);
        float ayt = 1.f + ((float)tly - pcy);
        float ayb = 1.f - ((float)bry - pcy);

        float c_tl = axt * ayt * m;
        float c_tr = axt * ayb * m;
        float c_bl = axb * ayt * m;
        float c_br = axb * ayb * m;

        bool vtx = (tlx >= 1 && tlx <= 96);
        bool vbx = (brx >= 1 && brx <= 96);
        bool vty = (tly >= 1 && tly <= 96);
        bool vby = (bry >= 1 && bry <= 96);

        int a_tl = (tlx - 1) * WW + (tly - 1);
        int a_tr = (tlx - 1) * WW + (bry - 1);
        int a_bl = (brx - 1) * WW + (tly - 1);
        int a_br = (brx - 1) * WW + (bry - 1);
        if (!(vtx && vty)) { c_tl = 0.f; a_tl = 0; }
        if (!(vtx && vby)) { c_tr = 0.f; a_tr = 0; }
        if (!(vbx && vty)) { c_bl = 0.f; a_bl = 0; }
        if (!(vbx && vby)) { c_br = 0.f; a_br = 0; }

        // ---- gather 32 channels (NCHW, warp-coalesced), split hi/lo ----
        uint2* arow = (uint2*)(Asm + pxl * AS2);
        #pragma unroll 2
        for (int it = 0; it < 8; it++) {
            const float* x0 = xg + (size_t)(4 * it) * HW;
            float t0 = c_tl * __ldg(x0 + a_tl) + c_tr * __ldg(x0 + a_tr)
                     + c_bl * __ldg(x0 + a_bl) + c_br * __ldg(x0 + a_br);
            const float* x1 = x0 + HW;
            float t1 = c_tl * __ldg(x1 + a_tl) + c_tr * __ldg(x1 + a_tr)
                     + c_bl * __ldg(x1 + a_bl) + c_br * __ldg(x1 + a_br);
            const float* x2 = x1 + HW;
            float t2 = c_tl * __ldg(x2 + a_tl) + c_tr * __ldg(x2 + a_tr)
                     + c_bl * __ldg(x2 + a_bl) + c_br * __ldg(x2 + a_br);
            const float* x3 = x2 + HW;
            float t3 = c_tl * __ldg(x3 + a_tl) + c_tr * __ldg(x3 + a_tr)
                     + c_bl * __ldg(x3 + a_bl) + c_br * __ldg(x3 + a_br);
            uint32_t hp0, lp0, hp1, lp1;
            split2(t0, t1, hp0, lp0);
            split2(t2, t3, hp1, lp1);
            arow[chalf * 8 + it]      = make_uint2(hp0, hp1);
            arow[16 + chalf * 8 + it] = make_uint2(lp0, lp1);
        }
        __syncthreads();

        // ---- 12 K-steps of m16n8k16 ----
        #pragma unroll
        for (int s = 0; s < 12; s++) {
            const int s3 = (s & 3) * 16;
            const int ka = s3 + ((s >= 4 && s < 8) ? 64 : 0);
            const int kb = s3 + ((s >= 8) ? 64 : 0);
            uint32_t a[2][4];
            ldmatrix_x4(a[0], aAddr[0] + ka * 2);
            ldmatrix_x4(a[1], aAddr[1] + ka * 2);
            #pragma unroll
            for (int nt = 0; nt < 4; nt++) {
                uint32_t b0, b1;
                ldmatrix_x2(b0, b1, bAddr[nt] + kb * 2);
                mma_bf16(acc[0][nt], a[0], b0, b1);
                mma_bf16(acc[1][nt], a[1], b0, b1);
            }
        }
        __syncthreads();
    }

    // ---- epilogue ----
    #pragma unroll
    for (int mt = 0; mt < 2; mt++) {
        int prow = blockIdx.x * 128 + rowsBase + mt * 16 + g;
        int pb0 = prow / HW,       pr0 = prow % HW;
        int pb1 = (prow + 8) / HW, pr1 = (prow + 8) % HW;
        float* o0 = out + (size_t)pb0 * OO * HW + pr0;
        float* o1 = out + (size_t)pb1 * OO * HW + pr1;
        #pragma unroll
        for (int nt = 0; nt < 4; nt++) {
            int oc = nhalf * 32 + nt * 8 + q * 2;
            float bb0 = cb[oc], bb1 = cb[oc + 1];
            o0[(size_t)oc * HW]       = acc[mt][nt][0] + bb0;
            o0[(size_t)(oc + 1) * HW] = acc[mt][nt][1] + bb1;
            o1[(size_t)oc * HW]       = acc[mt][nt][2] + bb0;
            o1[(size_t)(oc + 1) * HW] = acc[mt][nt][3] + bb1;
        }
    }
}

extern "C" void kernel_launch(void* const* d_in, const int* in_sizes, int n_in,
                              void* d_out, int out_size) {
    const float* x  = (const float*)d_in[0];
    const float* ow = (const float*)d_in[1];
    const float* ob = (const float*)d_in[2];
    const float* mw = (const float*)d_in[3];
    const float* mb = (const float*)d_in[4];
    const float* cw = (const float*)d_in[5];
    const float* cb = (const float*)d_in[6];
    float* out = (float*)d_out;

    const int smem1 = (128 * AS2 + 32 * BS2) * 2;  // 43520 B
    const int smem2 = (128 * AS2 + 64 * BS2) * 2;  // 52224 B
    cudaFuncSetAttribute(k_offconv_mma, cudaFuncAttributeMaxDynamicSharedMemorySize, smem1);
    cudaFuncSetAttribute(k_deform_mma,  cudaFuncAttributeMaxDynamicSharedMemorySize, smem2);

    k_prepw<<<432, 256>>>(cw, ow, mw);
    k_offconv_mma<<<PIXELS / 128, 256, smem1>>>(x, ob, mb);
    k_deform_mma<<<PIXELS / 128, 256, smem2>>>(x, cb, out);
}

// round 13
// speedup vs baseline: 2.0231x; 1.0142x over previous
#include <cuda_runtime.h>
#include <cuda_bf16.h>
#include <math.h>
#include <cstdint>

#define BB 8
#define CC 64
#define OO 64
#define HH 96
#define WW 96
#define NN 9
#define HW (HH*WW)            // 9216
#define PIXELS (BB*HH*WW)     // 73728
#define SCR_CH 27

// offset (18) + modulation-raw (9) planes, layout [ch][pixel], bias included
__device__ float g_scr[SCR_CH * PIXELS];
// prepped B for deform: [tap][o(64)][k(128)] bf16, k = [whi(64) | wlo(64)]
__device__ __align__(16) unsigned short g_Bw[NN * 64 * 128];
// prepped B for offconv: [tap][o(32, 27 used)][k(128)] bf16, k = [whi | wlo]
__device__ __align__(16) unsigned short g_Bw2[NN * 32 * 128];

__device__ __forceinline__ void mma_bf16(float* d, const uint32_t* a,
                                         uint32_t b0, uint32_t b1) {
    asm volatile(
        "mma.sync.aligned.m16n8k16.row.col.f32.bf16.bf16.f32 "
        "{%0,%1,%2,%3}, {%4,%5,%6,%7}, {%8,%9}, {%0,%1,%2,%3};"
        : "+f"(d[0]), "+f"(d[1]), "+f"(d[2]), "+f"(d[3])
        : "r"(a[0]), "r"(a[1]), "r"(a[2]), "r"(a[3]), "r"(b0), "r"(b1));
}

__device__ __forceinline__ void ldmatrix_x4(uint32_t* r, uint32_t addr) {
    asm volatile(
        "ldmatrix.sync.aligned.m8n8.x4.shared.b16 {%0,%1,%2,%3}, [%4];"
        : "=r"(r[0]), "=r"(r[1]), "=r"(r[2]), "=r"(r[3]) : "r"(addr));
}
__device__ __forceinline__ void ldmatrix_x2(uint32_t& r0, uint32_t& r1,
                                            uint32_t addr) {
    asm volatile(
        "ldmatrix.sync.aligned.m8n8.x2.shared.b16 {%0,%1}, [%2];"
        : "=r"(r0), "=r"(r1) : "r"(addr));
}
__device__ __forceinline__ uint32_t smem_u32(const void* p) {
    uint32_t a;
    asm("{ .reg .u64 t; cvta.to.shared.u64 t, %1; cvt.u32.u64 %0, t; }"
        : "=r"(a) : "l"(p));
    return a;
}

// split two fp32 into packed bf16 hi + bf16 lo-residual
__device__ __forceinline__ void split2(float v0, float v1,
                                       uint32_t& hp, uint32_t& lp) {
    asm("cvt.rn.satfinite.bf16x2.f32 %0, %1, %2;" : "=r"(hp) : "f"(v1), "f"(v0));
    float h0 = __uint_as_float(hp << 16);
    float h1 = __uint_as_float(hp & 0xffff0000u);
    float l0 = v0 - h0, l1 = v1 - h1;
    asm("cvt.rn.satfinite.bf16x2.f32 %0, %1, %2;" : "=r"(lp) : "f"(l1), "f"(l0));
}

// ---------------------------------------------------------------------------
// Kernel P: build both B images (hi/lo split, both 128-wide [whi|wlo]).
// ---------------------------------------------------------------------------
__global__ void __launch_bounds__(256) k_prepw(
    const float* __restrict__ cw,
    const float* __restrict__ ow, const float* __restrict__ mw)
{
    int i = blockIdx.x * 256 + threadIdx.x;     // 432*256 = 110592
    if (i < NN * 64 * 128) {
        int n = i / (64 * 128);
        int rr = i % (64 * 128);
        int o = rr / 128;
        int k = rr % 128;
        int c = k & 63;
        float wv = cw[(o * CC + c) * NN + n];
        __nv_bfloat16 hi = __float2bfloat16(wv);
        __nv_bfloat16 val = (k < 64) ? hi
                          : __float2bfloat16(wv - __bfloat162float(hi));
        unsigned short u; memcpy(&u, &val, 2);
        g_Bw[i] = u;
    } else {
        int j = i - NN * 64 * 128;              // 9*32*128 = 36864
        int n = j / (32 * 128);
        int rr = j % (32 * 128);
        int o = rr / 128;
        int k = rr % 128;
        int c = k & 63;
        float wv = (o < 18) ? ow[(o * CC + c) * 9 + n]
                 : (o < 27) ? mw[((o - 18) * CC + c) * 9 + n] : 0.f;
        __nv_bfloat16 hi = __float2bfloat16(wv);
        __nv_bfloat16 val = (k < 64) ? hi
                          : __float2bfloat16(wv - __bfloat162float(hi));
        unsigned short u; memcpy(&u, &val, 2);
        g_Bw2[j] = u;
    }
}

#define AS2 136   // A row stride (68 words; mod 32 = 4 -> ldmatrix conflict-free)
#define BS2 136   // B row stride
#define ABUF (128 * AS2)   // elements per A buffer

// ---------------------------------------------------------------------------
// Kernel 1 (v13): offconv GEMM, double-buffered tap pipeline.
// ---------------------------------------------------------------------------
__global__ void __launch_bounds__(256, 2) k_offconv_mma(
    const float* __restrict__ x,
    const float* __restrict__ ob, const float* __restrict__ mb)
{
    extern __shared__ unsigned short sm[];
    const int BBUF = 32 * BS2;
    unsigned short* A0 = sm;                  // 2 x 34816 B
    unsigned short* B0 = sm + 2 * ABUF;       // 2 x 8704 B

    const int tid = threadIdx.x;
    const int wid = tid >> 5;
    const int lane = tid & 31;
    const int g = lane >> 2;
    const int q = lane & 3;

    const int pxl = tid & 127;
    const int chalf = tid >> 7;
    const int p = blockIdx.x * 128 + pxl;
    const int b = p / HW, r = p % HW;
    const int h = r / WW, w = r % WW;
    const float* xg = x + ((size_t)b * CC + chalf * 32) * HW;

    const uint32_t asm_b = smem_u32(A0);
    const uint32_t bsm_b = smem_u32(B0);
    const uint32_t AOFF = ABUF * 2, BOFF = BBUF * 2;   // bytes
    const int tA = lane >> 3, riA = lane & 7;
    const int rowsBase = (wid & 3) * 32;
    const int nhalf = wid >> 2;
    uint32_t aAddr[2];
    #pragma unroll
    for (int mt = 0; mt < 2; mt++) {
        int row = rowsBase + mt * 16 + (tA & 1) * 8 + riA;
        aAddr[mt] = asm_b + (uint32_t)(row * AS2 + (tA >> 1) * 8) * 2;
    }
    const int l16 = lane & 15;
    const int tB = l16 >> 3, riB = l16 & 7;
    uint32_t bAddr[2];
    #pragma unroll
    for (int nt = 0; nt < 2; nt++) {
        int row = (nhalf * 2 + nt) * 8 + riB;
        bAddr[nt] = bsm_b + (uint32_t)(row * BS2 + tB * 8) * 2;
    }

    float acc[2][2][4];
    #pragma unroll
    for (int mt = 0; mt < 2; mt++)
        #pragma unroll
        for (int nt = 0; nt < 2; nt++)
            #pragma unroll
            for (int e = 0; e < 4; e++) acc[mt][nt][e] = 0.f;

    auto fillB = [&](int n, int buf) {
        unsigned short* Bb = B0 + buf * BBUF;
        const uint4* src = (const uint4*)(g_Bw2 + n * 32 * 128);
        #pragma unroll
        for (int j = 0; j < 2; j++) {
            int i = tid + 256 * j;
            int row = i >> 4, c4 = i & 15;
            ((uint4*)(Bb + row * BS2))[c4] = __ldg(src + i);
        }
    };

    auto gatherA = [&](int n, int buf) {
        int dh = n / 3 - 1, dw = n % 3 - 1;
        int ih = h + dh, iw = w + dw;
        int off = ((unsigned)ih < HH && (unsigned)iw < WW) ? ih * WW + iw : -1;
        const float* xs = xg + off;
        uint2* arow = (uint2*)(A0 + buf * ABUF + pxl * AS2);
        if (off >= 0) {
            #pragma unroll 2
            for (int it = 0; it < 8; it++) {
                float t0 = __ldg(xs + (size_t)(4 * it) * HW);
                float t1 = __ldg(xs + (size_t)(4 * it + 1) * HW);
                float t2 = __ldg(xs + (size_t)(4 * it + 2) * HW);
                float t3 = __ldg(xs + (size_t)(4 * it + 3) * HW);
                uint32_t hp0, lp0, hp1, lp1;
                split2(t0, t1, hp0, lp0);
                split2(t2, t3, hp1, lp1);
                arow[chalf * 8 + it]      = make_uint2(hp0, hp1);
                arow[16 + chalf * 8 + it] = make_uint2(lp0, lp1);
            }
        } else {
            #pragma unroll
            for (int it = 0; it < 8; it++) {
                arow[chalf * 8 + it]      = make_uint2(0u, 0u);
                arow[16 + chalf * 8 + it] = make_uint2(0u, 0u);
            }
        }
    };

    fillB(0, 0);
    gatherA(0, 0);
    __syncthreads();

    #pragma unroll 1
    for (int n = 0; n < NN; n++) {
        int cur = n & 1;
        if (n + 1 < NN) { fillB(n + 1, cur ^ 1); gatherA(n + 1, cur ^ 1); }

        uint32_t aO = cur ? AOFF : 0u;
        uint32_t bO = cur ? BOFF : 0u;
        #pragma unroll
        for (int s = 0; s < 12; s++) {
            const int s3 = (s & 3) * 16;
            const int ka = s3 + ((s >= 4 && s < 8) ? 64 : 0);
            const int kb = s3 + ((s >= 8) ? 64 : 0);
            uint32_t a[2][4];
            ldmatrix_x4(a[0], aAddr[0] + aO + ka * 2);
            ldmatrix_x4(a[1], aAddr[1] + aO + ka * 2);
            #pragma unroll
            for (int nt = 0; nt < 2; nt++) {
                uint32_t b0, b1;
                ldmatrix_x2(b0, b1, bAddr[nt] + bO + kb * 2);
                mma_bf16(acc[0][nt], a[0], b0, b1);
                mma_bf16(acc[1][nt], a[1], b0, b1);
            }
        }
        __syncthreads();
    }

    // ---- epilogue -> g_scr[oc][pixel] (+bias), oc < 27 ----
    #pragma unroll
    for (int mt = 0; mt < 2; mt++) {
        int prow = blockIdx.x * 128 + rowsBase + mt * 16 + g;
        #pragma unroll
        for (int nt = 0; nt < 2; nt++) {
            int oc = nhalf * 16 + nt * 8 + q * 2;
            if (oc < 27) {
                float bias = (oc < 18) ? ob[oc] : mb[oc - 18];
                g_scr[(size_t)oc * PIXELS + prow]     = acc[mt][nt][0] + bias;
                g_scr[(size_t)oc * PIXELS + prow + 8] = acc[mt][nt][2] + bias;
            }
            if (oc + 1 < 27) {
                float bias = (oc + 1 < 18) ? ob[oc + 1] : mb[oc - 17];
                g_scr[(size_t)(oc + 1) * PIXELS + prow]     = acc[mt][nt][1] + bias;
                g_scr[(size_t)(oc + 1) * PIXELS + prow + 8] = acc[mt][nt][3] + bias;
            }
        }
    }
}

// ---------------------------------------------------------------------------
// Kernel 2 (v13): deform GEMM, double-buffered tap pipeline.
// ---------------------------------------------------------------------------
__global__ void __launch_bounds__(256, 2) k_deform_mma(
    const float* __restrict__ x, const float* __restrict__ cb,
    float* __restrict__ out)
{
    extern __shared__ unsigned short sm[];
    const int BBUF = 64 * BS2;
    unsigned short* A0 = sm;                  // 2 x 34816 B
    unsigned short* B0 = sm + 2 * ABUF;       // 2 x 17408 B

    const int tid = threadIdx.x;
    const int wid = tid >> 5;
    const int lane = tid & 31;
    const int g = lane >> 2;
    const int q = lane & 3;

    const int pxl = tid & 127;
    const int chalf = tid >> 7;
    const int p = blockIdx.x * 128 + pxl;
    const int b = p / HW, r = p % HW;
    const int h = r / WW, w = r % WW;
    const float* xg = x + ((size_t)b * CC + chalf * 32) * HW;

    const uint32_t asm_b = smem_u32(A0);
    const uint32_t bsm_b = smem_u32(B0);
    const uint32_t AOFF = ABUF * 2, BOFF = BBUF * 2;   // bytes
    const int tA = lane >> 3, riA = lane & 7;
    const int rowsBase = (wid & 3) * 32;
    const int nhalf = wid >> 2;
    uint32_t aAddr[2];
    #pragma unroll
    for (int mt = 0; mt < 2; mt++) {
        int row = rowsBase + mt * 16 + (tA & 1) * 8 + riA;
        aAddr[mt] = asm_b + (uint32_t)(row * AS2 + (tA >> 1) * 8) * 2;
    }
    const int l16 = lane & 15;
    const int tB = l16 >> 3, riB = l16 & 7;
    uint32_t bAddr[4];
    #pragma unroll
    for (int nt = 0; nt < 4; nt++) {
        int row = (nhalf * 4 + nt) * 8 + riB;
        bAddr[nt] = bsm_b + (uint32_t)(row * BS2 + tB * 8) * 2;
    }

    float acc[2][4][4];
    #pragma unroll
    for (int mt = 0; mt < 2; mt++)
        #pragma unroll
        for (int nt = 0; nt < 4; nt++)
            #pragma unroll
            for (int e = 0; e < 4; e++) acc[mt][nt][e] = 0.f;

    auto fillB = [&](int n, int buf) {
        unsigned short* Bb = B0 + buf * BBUF;
        const uint4* src = (const uint4*)(g_Bw + n * 64 * 128);
        #pragma unroll
        for (int j = 0; j < 4; j++) {
            int i = tid + 256 * j;
            int row = i >> 4, c4 = i & 15;
            ((uint4*)(Bb + row * BS2))[c4] = __ldg(src + i);
        }
    };

    auto gatherA = [&](int n, int buf) {
        float offx = g_scr[n * PIXELS + p];
        float offy = g_scr[(9 + n) * PIXELS + p];
        float mraw = g_scr[(18 + n) * PIXELS + p];
        float m = 1.f / (1.f + __expf(-mraw));

        float px = offx + (float)(h + 1) + (float)(n / 3 - 1);
        float py = offy + (float)(w + 1) + (float)(n % 3 - 1);

        float flx = floorf(px), fly = floorf(py);
        int tlx = max(min((int)flx, 97), 0);
        int brx = max(min((int)flx + 1, 97), 0);
        int tly = max(min((int)fly, 97), 0);
        int bry = max(min((int)fly + 1, 97), 0);
        float pcx = fminf(fmaxf(px, 0.f), 97.f);
        float pcy = fminf(fmaxf(py, 0.f), 97.f);

        float axt = 1.f + ((float)tlx - pcx);
        float axb = 1.f - ((float)brx - pcx);
        float ayt = 1.f + ((float)tly - pcy);
        float ayb = 1.f - ((float)bry - pcy);

        float c_tl = axt * ayt * m;
        float c_tr = axt * ayb * m;
        float c_bl = axb * ayt * m;
        float c_br = axb * ayb * m;

        bool vtx = (tlx >= 1 && tlx <= 96);
        bool vbx = (brx >= 1 && brx <= 96);
        bool vty = (tly >= 1 && tly <= 96);
        bool vby = (bry >= 1 && bry <= 96);

        int a_tl = (tlx - 1) * WW + (tly - 1);
        int a_tr = (tlx - 1) * WW + (bry - 1);
        int a_bl = (brx - 1) * WW + (tly - 1);
        int a_br = (brx - 1) * WW + (bry - 1);
        if (!(vtx && vty)) { c_tl = 0.f; a_tl = 0; }
        if (!(vtx && vby)) { c_tr = 0.f; a_tr = 0; }
        if (!(vbx && vty)) { c_bl = 0.f; a_bl = 0; }
        if (!(vbx && vby)) { c_br = 0.f; a_br = 0; }

        uint2* arow = (uint2*)(A0 + buf * ABUF + pxl * AS2);
        #pragma unroll 2
        for (int it = 0; it < 8; it++) {
            const float* x0 = xg + (size_t)(4 * it) * HW;
            float t0 = c_tl * __ldg(x0 + a_tl) + c_tr * __ldg(x0 + a_tr)
                     + c_bl * __ldg(x0 + a_bl) + c_br * __ldg(x0 + a_br);
            const float* x1 = x0 + HW;
            float t1 = c_tl * __ldg(x1 + a_tl) + c_tr * __ldg(x1 + a_tr)
                     + c_bl * __ldg(x1 + a_bl) + c_br * __ldg(x1 + a_br);
            const float* x2 = x1 + HW;
            float t2 = c_tl * __ldg(x2 + a_tl) + c_tr * __ldg(x2 + a_tr)
                     + c_bl * __ldg(x2 + a_bl) + c_br * __ldg(x2 + a_br);
            const float* x3 = x2 + HW;
            float t3 = c_tl * __ldg(x3 + a_tl) + c_tr * __ldg(x3 + a_tr)
                     + c_bl * __ldg(x3 + a_bl) + c_br * __ldg(x3 + a_br);
            uint32_t hp0, lp0, hp1, lp1;
            split2(t0, t1, hp0, lp0);
            split2(t2, t3, hp1, lp1);
            arow[chalf * 8 + it]      = make_uint2(hp0, hp1);
            arow[16 + chalf * 8 + it] = make_uint2(lp0, lp1);
        }
    };

    fillB(0, 0);
    gatherA(0, 0);
    __syncthreads();

    #pragma unroll 1
    for (int n = 0; n < NN; n++) {
        int cur = n & 1;
        if (n + 1 < NN) { fillB(n + 1, cur ^ 1); gatherA(n + 1, cur ^ 1); }

        uint32_t aO = cur ? AOFF : 0u;
        uint32_t bO = cur ? BOFF : 0u;
        #pragma unroll
        for (int s = 0; s < 12; s++) {
            const int s3 = (s & 3) * 16;
            const int ka = s3 + ((s >= 4 && s < 8) ? 64 : 0);
            const int kb = s3 + ((s >= 8) ? 64 : 0);
            uint32_t a[2][4];
            ldmatrix_x4(a[0], aAddr[0] + aO + ka * 2);
            ldmatrix_x4(a[1], aAddr[1] + aO + ka * 2);
            #pragma unroll
            for (int nt = 0; nt < 4; nt++) {
                uint32_t b0, b1;
                ldmatrix_x2(b0, b1, bAddr[nt] + bO + kb * 2);
                mma_bf16(acc[0][nt], a[0], b0, b1);
                mma_bf16(acc[1][nt], a[1], b0, b1);
            }
        }
        __syncthreads();
    }

    // ---- epilogue ----
    #pragma unroll
    for (int mt = 0; mt < 2; mt++) {
        int prow = blockIdx.x * 128 + rowsBase + mt * 16 + g;
        int pb0 = prow / HW,       pr0 = prow % HW;
        int pb1 = (prow + 8) / HW, pr1 = (prow + 8) % HW;
        float* o0 = out + (size_t)pb0 * OO * HW + pr0;
        float* o1 = out + (size_t)pb1 * OO * HW + pr1;
        #pragma unroll
        for (int nt = 0; nt < 4; nt++) {
            int oc = nhalf * 32 + nt * 8 + q * 2;
            float bb0 = cb[oc], bb1 = cb[oc + 1];
            o0[(size_t)oc * HW]       = acc[mt][nt][0] + bb0;
            o0[(size_t)(oc + 1) * HW] = acc[mt][nt][1] + bb1;
            o1[(size_t)oc * HW]       = acc[mt][nt][2] + bb0;
            o1[(size_t)(oc + 1) * HW] = acc[mt][nt][3] + bb1;
        }
    }
}

extern "C" void kernel_launch(void* const* d_in, const int* in_sizes, int n_in,
                              void* d_out, int out_size) {
    const float* x  = (const float*)d_in[0];
    const float* ow = (const float*)d_in[1];
    const float* ob = (const float*)d_in[2];
    const float* mw = (const float*)d_in[3];
    const float* mb = (const float*)d_in[4];
    const float* cw = (const float*)d_in[5];
    const float* cb = (const float*)d_in[6];
    float* out = (float*)d_out;

    const int smem1 = (2 * ABUF + 2 * 32 * BS2) * 2;   // 87040 B
    const int smem2 = (2 * ABUF + 2 * 64 * BS2) * 2;   // 104448 B
    cudaFuncSetAttribute(k_offconv_mma, cudaFuncAttributeMaxDynamicSharedMemorySize, smem1);
    cudaFuncSetAttribute(k_deform_mma,  cudaFuncAttributeMaxDynamicSharedMemorySize, smem2);

    k_prepw<<<432, 256>>>(cw, ow, mw);
    k_offconv_mma<<<PIXELS / 128, 256, smem1>>>(x, ob, mb);
    k_deform_mma<<<PIXELS / 128, 256, smem2>>>(x, cb, out);
}